// round 2
// baseline (speedup 1.0000x reference)
#include <cuda_runtime.h>
#include <math.h>

#define B_      2
#define S_      1024
#define DIN     2048
#define DOUT    2048
#define H_      8
#define DK_     64
#define DV_     128
#define CONVDIM 2560
#define GDIM    1024
#define HTOT    3584   /* CONVDIM + GDIM */
#define MTOT    2048   /* B_*S_ */
#define BH_     16     /* B_*H_ */
#define KGROUPS 8      /* DK_/8 */

/* ------------------------------------------------------------------ */
/* scratch (device globals; no runtime allocation allowed)            */
/* ------------------------------------------------------------------ */
__device__ float g_h [MTOT * HTOT];            /* post in-proj        */
__device__ float g_q [BH_ * S_ * DK_];
__device__ float g_k [BH_ * S_ * DK_];         /* normalized k        */
__device__ float g_g [BH_ * S_ * DK_];         /* sigmoid(f')         */
__device__ float g_v [BH_ * S_ * DV_];
__device__ float g_yp[KGROUPS * BH_ * S_ * DV_]; /* partial y per kg  */
__device__ float g_y2[MTOT * GDIM];            /* gated+normed y      */

__device__ __forceinline__ float sigmoidf_(float x) { return 1.f / (1.f + expf(-x)); }

/* ------------------------------------------------------------------ */
/* SGEMM (NT): C[M,N] = A[M,K] * B[N,K]^T (+ bias[N])                 */
/* 128x128 tile, k-tile 16, 256 threads, 8x8 microtile                */
/* ------------------------------------------------------------------ */
__global__ void __launch_bounds__(256)
sgemm_nt(const float* __restrict__ A, const float* __restrict__ B,
         const float* __restrict__ bias, float* __restrict__ C,
         int M, int N, int K, int hasBias)
{
    __shared__ float As[16][132];
    __shared__ float Bs[16][132];

    const int tid = threadIdx.x;
    const int bm = blockIdx.y * 128;
    const int bn = blockIdx.x * 128;
    const int tm = (tid >> 4) << 3;   /* 0..120 */
    const int tn = (tid & 15) << 3;   /* 0..120 */

    float acc[8][8];
#pragma unroll
    for (int i = 0; i < 8; i++)
#pragma unroll
        for (int j = 0; j < 8; j++) acc[i][j] = 0.f;

    const int lr = tid >> 2;          /* 0..63 */
    const int lk = (tid & 3) << 2;    /* 0,4,8,12 */
    const float* Ap = A + (size_t)(bm + lr) * K + lk;
    const float* Bp = B + (size_t)(bn + lr) * K + lk;

    for (int k0 = 0; k0 < K; k0 += 16) {
        float4 a0 = *(const float4*)(Ap + k0);
        float4 a1 = *(const float4*)(Ap + (size_t)64 * K + k0);
        float4 b0 = *(const float4*)(Bp + k0);
        float4 b1 = *(const float4*)(Bp + (size_t)64 * K + k0);

        As[lk + 0][lr] = a0.x; As[lk + 1][lr] = a0.y; As[lk + 2][lr] = a0.z; As[lk + 3][lr] = a0.w;
        As[lk + 0][lr + 64] = a1.x; As[lk + 1][lr + 64] = a1.y; As[lk + 2][lr + 64] = a1.z; As[lk + 3][lr + 64] = a1.w;
        Bs[lk + 0][lr] = b0.x; Bs[lk + 1][lr] = b0.y; Bs[lk + 2][lr] = b0.z; Bs[lk + 3][lr] = b0.w;
        Bs[lk + 0][lr + 64] = b1.x; Bs[lk + 1][lr + 64] = b1.y; Bs[lk + 2][lr + 64] = b1.z; Bs[lk + 3][lr + 64] = b1.w;
        __syncthreads();

#pragma unroll
        for (int kk = 0; kk < 16; kk++) {
            float ar[8], br[8];
            *(float4*)(ar)     = *(const float4*)(&As[kk][tm]);
            *(float4*)(ar + 4) = *(const float4*)(&As[kk][tm + 4]);
            *(float4*)(br)     = *(const float4*)(&Bs[kk][tn]);
            *(float4*)(br + 4) = *(const float4*)(&Bs[kk][tn + 4]);
#pragma unroll
            for (int i = 0; i < 8; i++)
#pragma unroll
                for (int j = 0; j < 8; j++)
                    acc[i][j] = fmaf(ar[i], br[j], acc[i][j]);
        }
        __syncthreads();
    }

    float bb[8];
#pragma unroll
    for (int j = 0; j < 8; j++) bb[j] = hasBias ? bias[bn + tn + j] : 0.f;

#pragma unroll
    for (int i = 0; i < 8; i++) {
        float* crow = C + (size_t)(bm + tm + i) * N + bn + tn;
#pragma unroll
        for (int j = 0; j < 8; j++) crow[j] = acc[i][j] + bb[j];
    }
}

/* ------------------------------------------------------------------ */
/* depthwise causal conv (K=4) + SiLU + split + k-norm + gate precomp */
/* one block per (b,s)                                                */
/* ------------------------------------------------------------------ */
__global__ void __launch_bounds__(256)
conv_split_kernel(const float* __restrict__ cw, const float* __restrict__ cb,
                  const float* __restrict__ fm, const float* __restrict__ fb)
{
    const int bs = blockIdx.x;
    const int b = bs >> 10;
    const int s = bs & 1023;

    __shared__ float yc[CONVDIM];
    __shared__ float rn[H_];
    __shared__ float fms[H_];

    const float* hrow = g_h + (size_t)bs * HTOT;

    for (int c = threadIdx.x; c < CONVDIM; c += 256) {
        const float4 w4 = *(const float4*)(cw + c * 4);
        float acc = cb[c];
        if (s >= 3) {
            acc += hrow[-3 * HTOT + c] * w4.x;
            acc += hrow[-2 * HTOT + c] * w4.y;
            acc += hrow[-1 * HTOT + c] * w4.z;
            acc += hrow[c] * w4.w;
        } else {
            if (s >= 3) acc += hrow[-3 * HTOT + c] * w4.x;
            if (s >= 2) acc += hrow[-2 * HTOT + c] * w4.y;
            if (s >= 1) acc += hrow[-1 * HTOT + c] * w4.z;
            acc += hrow[c] * w4.w;
        }
        yc[c] = acc * sigmoidf_(acc);   /* SiLU */
    }
    __syncthreads();

    /* k-norm per head: warp w handles head w (8 warps) */
    const int wid = threadIdx.x >> 5;
    const int lane = threadIdx.x & 31;
    {
        float a = yc[512 + wid * 64 + lane];
        float b2 = yc[512 + wid * 64 + 32 + lane];
        float ss = a * a + b2 * b2;
#pragma unroll
        for (int o = 16; o; o >>= 1) ss += __shfl_xor_sync(0xffffffffu, ss, o);
        if (lane == 0) {
            rn[wid] = rsqrtf(ss + 1e-12f);
            fms[wid] = 2.f * sigmoidf_(fm[wid]);
        }
    }
    __syncthreads();

    for (int c = threadIdx.x; c < CONVDIM; c += 256) {
        float val = yc[c];
        if (c < 512) {
            int hd = c >> 6, dk = c & 63;
            g_q[((size_t)(b * H_ + hd) * S_ + s) * DK_ + dk] = val;
        } else if (c < 1024) {
            int cc = c - 512; int hd = cc >> 6, dk = cc & 63;
            g_k[((size_t)(b * H_ + hd) * S_ + s) * DK_ + dk] = val * rn[hd];
        } else if (c < 2048) {
            int cc = c - 1024; int hd = cc >> 7, dv = cc & 127;
            g_v[((size_t)(b * H_ + hd) * S_ + s) * DV_ + dv] = val;
        } else {
            int cc = c - 2048; int hd = cc >> 6, dk = cc & 63;
            float fv = fms[hd] * (val + fb[hd * DK_ + dk]);
            g_g[((size_t)(b * H_ + hd) * S_ + s) * DK_ + dk] = sigmoidf_(fv);
        }
    }
}

/* ------------------------------------------------------------------ */
/* recurrent scan: block = (kg, bh). 8 k-rows per block, 256 threads. */
/* thread (khalf = tid>>7 owns 4 k-rows; vcol = tid&127 owns 1 col)   */
/* smem: WT[128][132] (W^T, padded), S double-buffer, y partial buf.  */
/* ------------------------------------------------------------------ */
#define SCAN_SMEM ((128 * 132 + 2 * 1024 + 2 * 128) * 4)

__global__ void __launch_bounds__(256)
scan_kernel(const float* __restrict__ W)
{
    extern __shared__ float sm[];
    float* WT  = sm;                 /* 128*132 */
    float* Ssm = sm + 128 * 132;     /* 2*8*128 */
    float* yps = Ssm + 2048;         /* 2*128   */

    const int bh = blockIdx.y;
    const int kg = blockIdx.x;
    const int h  = bh & 7;
    const int tid = threadIdx.x;
    const int vcol  = tid & 127;
    const int khalf = tid >> 7;

    /* load W_h transposed: WT[w][u] = W[h][u][w], pitch 132 */
    const float* Wh = W + (size_t)h * DV_ * DV_;
    for (int i = tid; i < DV_ * DV_; i += 256) {
        int u = i >> 7, w = i & 127;
        WT[w * 132 + u] = Wh[i];
    }
    for (int i = tid; i < 2048; i += 256) Ssm[i] = 0.f;
    __syncthreads();

    float s0 = 0.f, s1 = 0.f, s2 = 0.f, s3 = 0.f;

    const float* vb = g_v + (size_t)bh * S_ * DV_;
    const size_t qoffb = (size_t)bh * S_ * DK_ + kg * 8 + khalf * 4;
    const float* qb = g_q + qoffb;
    const float* kb = g_k + qoffb;
    const float* gb = g_g + qoffb;
    float* yo = g_yp + ((size_t)(kg * BH_ + bh) * S_) * DV_;

    const float4* wr = (const float4*)(WT + vcol * 132);
    int cur = 0;

    for (int t = 0; t < S_; t++) {
        const float4* Sb = (const float4*)(Ssm + cur * 1024 + khalf * 512);
        float p0 = 0.f, p1 = 0.f, p2 = 0.f, p3 = 0.f;
#pragma unroll
        for (int ug = 0; ug < 32; ug++) {
            float4 w4 = wr[ug];
            float4 a0 = Sb[ug];
            float4 a1 = Sb[32 + ug];
            float4 a2 = Sb[64 + ug];
            float4 a3 = Sb[96 + ug];
            p0 = fmaf(w4.x, a0.x, p0); p0 = fmaf(w4.y, a0.y, p0);
            p0 = fmaf(w4.z, a0.z, p0); p0 = fmaf(w4.w, a0.w, p0);
            p1 = fmaf(w4.x, a1.x, p1); p1 = fmaf(w4.y, a1.y, p1);
            p1 = fmaf(w4.z, a1.z, p1); p1 = fmaf(w4.w, a1.w, p1);
            p2 = fmaf(w4.x, a2.x, p2); p2 = fmaf(w4.y, a2.y, p2);
            p2 = fmaf(w4.z, a2.z, p2); p2 = fmaf(w4.w, a2.w, p2);
            p3 = fmaf(w4.x, a3.x, p3); p3 = fmaf(w4.y, a3.y, p3);
            p3 = fmaf(w4.z, a3.z, p3); p3 = fmaf(w4.w, a3.w, p3);
        }

        float vt = vb[t * DV_ + vcol];
        float4 q4 = *(const float4*)(qb + t * DK_);
        float4 k4 = *(const float4*)(kb + t * DK_);
        float4 g4 = *(const float4*)(gb + t * DK_);

        float c0 = tanhf(vt + p0); s0 = fmaf(g4.x, s0, k4.x * c0);
        float c1 = tanhf(vt + p1); s1 = fmaf(g4.y, s1, k4.y * c1);
        float c2 = tanhf(vt + p2); s2 = fmaf(g4.z, s2, k4.z * c2);
        float c3 = tanhf(vt + p3); s3 = fmaf(g4.w, s3, k4.w * c3);

        float ypv = q4.x * s0 + q4.y * s1 + q4.z * s2 + q4.w * s3;

        int nxt = cur ^ 1;
        float* Sw = Ssm + nxt * 1024 + khalf * 512 + vcol;
        Sw[0] = s0; Sw[128] = s1; Sw[256] = s2; Sw[384] = s3;
        if (khalf) yps[(t & 1) * 128 + vcol] = ypv;
        __syncthreads();
        if (!khalf) yo[t * DV_ + vcol] = ypv + yps[(t & 1) * 128 + vcol];
        cur = nxt;
    }
}

/* ------------------------------------------------------------------ */
/* reduce partials + v*D + gate*silu + RMSNorm*g_w                    */
/* one block per (b,s)                                                */
/* ------------------------------------------------------------------ */
__global__ void __launch_bounds__(256)
mix_kernel(const float* __restrict__ Dm, const float* __restrict__ gw)
{
    const int bs = blockIdx.x;
    const int b = bs >> 10;
    const int s = bs & 1023;

    __shared__ float ybuf[GDIM];
    __shared__ float red[8];

    float local = 0.f;
    for (int c = threadIdx.x; c < GDIM; c += 256) {
        int hd = c >> 7, dv = c & 127;
        size_t bh = (size_t)b * H_ + hd;
        float acc = 0.f;
#pragma unroll
        for (int kg = 0; kg < KGROUPS; kg++)
            acc += g_yp[(((size_t)kg * BH_ + bh) * S_ + s) * DV_ + dv];
        float vv = g_v[(bh * S_ + s) * DV_ + dv];
        acc = fmaf(vv, Dm[hd * DV_ + dv], acc);
        float gt = g_h[(size_t)bs * HTOT + CONVDIM + c];
        acc *= gt * sigmoidf_(gt);
        ybuf[c] = acc;
        local = fmaf(acc, acc, local);
    }
#pragma unroll
    for (int o = 16; o; o >>= 1) local += __shfl_xor_sync(0xffffffffu, local, o);
    if ((threadIdx.x & 31) == 0) red[threadIdx.x >> 5] = local;
    __syncthreads();
    if (threadIdx.x == 0) {
        float tot = 0.f;
#pragma unroll
        for (int i = 0; i < 8; i++) tot += red[i];
        red[0] = rsqrtf(tot / (float)GDIM + 1e-6f);
    }
    __syncthreads();
    float rms = red[0];
    for (int c = threadIdx.x; c < GDIM; c += 256)
        g_y2[(size_t)bs * GDIM + c] = ybuf[c] * rms * gw[c];
}

/* ------------------------------------------------------------------ */
extern "C" void kernel_launch(void* const* d_in, const int* in_sizes, int n_in,
                              void* d_out, int out_size)
{
    const float* x    = (const float*)d_in[0];
    const float* w_in = (const float*)d_in[1];
    const float* b_in = (const float*)d_in[2];
    const float* cw   = (const float*)d_in[3];
    const float* cb   = (const float*)d_in[4];
    const float* Dm   = (const float*)d_in[5];
    const float* Wst  = (const float*)d_in[6];
    const float* fm   = (const float*)d_in[7];
    const float* fb   = (const float*)d_in[8];
    const float* gw   = (const float*)d_in[9];
    const float* wout = (const float*)d_in[10];
    float* out = (float*)d_out;

    void *ph = 0, *py2 = 0;
    cudaGetSymbolAddress(&ph, g_h);
    cudaGetSymbolAddress(&py2, g_y2);

    cudaFuncSetAttribute(scan_kernel, cudaFuncAttributeMaxDynamicSharedMemorySize, SCAN_SMEM);

    /* 1. in-projection: h = x @ w_in^T + b_in */
    sgemm_nt<<<dim3(HTOT / 128, MTOT / 128), 256>>>(x, w_in, b_in, (float*)ph,
                                                    MTOT, HTOT, DIN, 1);
    /* 2. conv + silu + split + knorm + gate precompute */
    conv_split_kernel<<<MTOT, 256>>>(cw, cb, fm, fb);
    /* 3. recurrent scan (128 independent blocks) */
    scan_kernel<<<dim3(KGROUPS, BH_), 256, SCAN_SMEM>>>(Wst);
    /* 4. reduce + v*D + gate + RMSNorm */
    mix_kernel<<<MTOT, 256>>>(Dm, gw);
    /* 5. out-projection: out = y2 @ w_out^T */
    sgemm_nt<<<dim3(DOUT / 128, MTOT / 128), 256>>>((const float*)py2, wout, 0, out,
                                                    MTOT, DOUT, GDIM, 0);
}

// round 3
// speedup vs baseline: 1.1120x; 1.1120x over previous
#include <cuda_runtime.h>
#include <math.h>

#define B_      2
#define S_      1024
#define DIN     2048
#define DOUT    2048
#define H_      8
#define DK_     64
#define DV_     128
#define CONVDIM 2560
#define GDIM    1024
#define HTOT    3584   /* CONVDIM + GDIM */
#define MTOT    2048   /* B_*S_ */
#define BH_     16     /* B_*H_ */
#define KGROUPS 8      /* DK_/8 */

/* ------------------------------------------------------------------ */
/* scratch (device globals; no runtime allocation allowed)            */
/* ------------------------------------------------------------------ */
__device__ float g_h [MTOT * HTOT];            /* post in-proj        */
__device__ float g_q [BH_ * S_ * DK_];
__device__ float g_k [BH_ * S_ * DK_];         /* normalized k        */
__device__ float g_g [BH_ * S_ * DK_];         /* sigmoid(f')         */
__device__ float g_v [BH_ * S_ * DV_];
__device__ float g_yp[KGROUPS * BH_ * S_ * DV_]; /* partial y per kg  */
__device__ float g_y2[MTOT * GDIM];            /* gated+normed y      */

__device__ __forceinline__ float sigmoidf_(float x) { return 1.f / (1.f + expf(-x)); }

__device__ __forceinline__ unsigned tf32_(float x) {
    unsigned r;
    asm("cvt.rna.tf32.f32 %0, %1;" : "=r"(r) : "f"(x));
    return r;
}

/* ------------------------------------------------------------------ */
/* TF32 tensor-core GEMM (NT): C[M,N] = A[M,K] * B[N,K]^T (+ bias[N]) */
/* 128x128 block tile, BK=32, 256 threads = 8 warps (2M x 4N),        */
/* warp tile 64x32 via m16n8k8, reg-prefetch double buffer.           */
/* Requires M%128==0, N%128==0, K%32==0.                              */
/* ------------------------------------------------------------------ */
#define GPITCH 36

__global__ void __launch_bounds__(256)
gemm_tf32(const float* __restrict__ A, const float* __restrict__ B,
          const float* __restrict__ bias, float* __restrict__ C,
          int M, int N, int K, int hasBias)
{
    __shared__ unsigned As[128 * GPITCH];
    __shared__ unsigned Bs[128 * GPITCH];

    const int tid  = threadIdx.x;
    const int lane = tid & 31;
    const int wid  = tid >> 5;
    const int warpM = wid & 1;        /* 0..1 */
    const int warpN = wid >> 1;       /* 0..3 */
    const int bm = blockIdx.y * 128;
    const int bn = blockIdx.x * 128;

    /* loader mapping: row = tid/2 (0..127), kbase = (tid&1)*16 */
    const int lrow  = tid >> 1;
    const int lkb   = (tid & 1) << 4;
    const float* Ag = A + (size_t)(bm + lrow) * K + lkb;
    const float* Bg = B + (size_t)(bn + lrow) * K + lkb;

    float acc[4][4][4];
#pragma unroll
    for (int i = 0; i < 4; i++)
#pragma unroll
        for (int j = 0; j < 4; j++)
#pragma unroll
            for (int r = 0; r < 4; r++) acc[i][j][r] = 0.f;

    const int nkt = K >> 5;

    /* prologue: load tile 0 */
    float4 pa[4], pb[4];
#pragma unroll
    for (int i = 0; i < 4; i++) {
        pa[i] = *(const float4*)(Ag + i * 4);
        pb[i] = *(const float4*)(Bg + i * 4);
    }

    for (int kt = 0; kt < nkt; kt++) {
        /* store staged tile to smem (tf32-converted) */
#pragma unroll
        for (int i = 0; i < 4; i++) {
            unsigned* pA = &As[lrow * GPITCH + lkb + i * 4];
            pA[0] = tf32_(pa[i].x); pA[1] = tf32_(pa[i].y);
            pA[2] = tf32_(pa[i].z); pA[3] = tf32_(pa[i].w);
            unsigned* pB = &Bs[lrow * GPITCH + lkb + i * 4];
            pB[0] = tf32_(pb[i].x); pB[1] = tf32_(pb[i].y);
            pB[2] = tf32_(pb[i].z); pB[3] = tf32_(pb[i].w);
        }
        __syncthreads();

        /* prefetch next tile into registers */
        if (kt + 1 < nkt) {
            const float* Agn = Ag + (kt + 1) * 32;
            const float* Bgn = Bg + (kt + 1) * 32;
#pragma unroll
            for (int i = 0; i < 4; i++) {
                pa[i] = *(const float4*)(Agn + i * 4);
                pb[i] = *(const float4*)(Bgn + i * 4);
            }
        }

        /* compute: 4 k-steps of 8 */
#pragma unroll
        for (int ks = 0; ks < 4; ks++) {
            const int kc = ks * 8 + (lane & 3);
            unsigned af[4][4], bf[4][2];
#pragma unroll
            for (int mt = 0; mt < 4; mt++) {
                int r = warpM * 64 + mt * 16 + (lane >> 2);
                af[mt][0] = As[r * GPITCH + kc];
                af[mt][1] = As[(r + 8) * GPITCH + kc];
                af[mt][2] = As[r * GPITCH + kc + 4];
                af[mt][3] = As[(r + 8) * GPITCH + kc + 4];
            }
#pragma unroll
            for (int nt = 0; nt < 4; nt++) {
                int r = warpN * 32 + nt * 8 + (lane >> 2);
                bf[nt][0] = Bs[r * GPITCH + kc];
                bf[nt][1] = Bs[r * GPITCH + kc + 4];
            }
#pragma unroll
            for (int mt = 0; mt < 4; mt++)
#pragma unroll
                for (int nt = 0; nt < 4; nt++) {
                    asm volatile(
                        "mma.sync.aligned.m16n8k8.row.col.f32.tf32.tf32.f32 "
                        "{%0,%1,%2,%3}, {%4,%5,%6,%7}, {%8,%9}, {%0,%1,%2,%3};"
                        : "+f"(acc[mt][nt][0]), "+f"(acc[mt][nt][1]),
                          "+f"(acc[mt][nt][2]), "+f"(acc[mt][nt][3])
                        : "r"(af[mt][0]), "r"(af[mt][1]),
                          "r"(af[mt][2]), "r"(af[mt][3]),
                          "r"(bf[nt][0]), "r"(bf[nt][1]));
                }
        }
        __syncthreads();
    }

    /* epilogue */
#pragma unroll
    for (int mt = 0; mt < 4; mt++) {
        int row0 = bm + warpM * 64 + mt * 16 + (lane >> 2);
#pragma unroll
        for (int nt = 0; nt < 4; nt++) {
            int col = bn + warpN * 32 + nt * 8 + ((lane & 3) << 1);
            float b0 = hasBias ? bias[col] : 0.f;
            float b1 = hasBias ? bias[col + 1] : 0.f;
            float2 v0 = make_float2(acc[mt][nt][0] + b0, acc[mt][nt][1] + b1);
            float2 v1 = make_float2(acc[mt][nt][2] + b0, acc[mt][nt][3] + b1);
            *(float2*)(C + (size_t)row0 * N + col) = v0;
            *(float2*)(C + (size_t)(row0 + 8) * N + col) = v1;
        }
    }
}

/* ------------------------------------------------------------------ */
/* depthwise causal conv (K=4) + SiLU + split + k-norm + gate precomp */
/* ------------------------------------------------------------------ */
__global__ void __launch_bounds__(256)
conv_split_kernel(const float* __restrict__ cw, const float* __restrict__ cb,
                  const float* __restrict__ fm, const float* __restrict__ fb)
{
    const int bs = blockIdx.x;
    const int b = bs >> 10;
    const int s = bs & 1023;

    __shared__ float yc[CONVDIM];
    __shared__ float rn[H_];
    __shared__ float fms[H_];

    const float* hrow = g_h + (size_t)bs * HTOT;

    for (int c = threadIdx.x; c < CONVDIM; c += 256) {
        const float4 w4 = *(const float4*)(cw + c * 4);
        float acc = cb[c];
        if (s >= 3) acc += hrow[-3 * HTOT + c] * w4.x;
        if (s >= 2) acc += hrow[-2 * HTOT + c] * w4.y;
        if (s >= 1) acc += hrow[-1 * HTOT + c] * w4.z;
        acc += hrow[c] * w4.w;
        yc[c] = acc * sigmoidf_(acc);   /* SiLU */
    }
    __syncthreads();

    const int wid = threadIdx.x >> 5;
    const int lane = threadIdx.x & 31;
    {
        float a = yc[512 + wid * 64 + lane];
        float b2 = yc[512 + wid * 64 + 32 + lane];
        float ss = a * a + b2 * b2;
#pragma unroll
        for (int o = 16; o; o >>= 1) ss += __shfl_xor_sync(0xffffffffu, ss, o);
        if (lane == 0) {
            rn[wid] = rsqrtf(ss + 1e-12f);
            fms[wid] = 2.f * sigmoidf_(fm[wid]);
        }
    }
    __syncthreads();

    for (int c = threadIdx.x; c < CONVDIM; c += 256) {
        float val = yc[c];
        if (c < 512) {
            int hd = c >> 6, dk = c & 63;
            g_q[((size_t)(b * H_ + hd) * S_ + s) * DK_ + dk] = val;
        } else if (c < 1024) {
            int cc = c - 512; int hd = cc >> 6, dk = cc & 63;
            g_k[((size_t)(b * H_ + hd) * S_ + s) * DK_ + dk] = val * rn[hd];
        } else if (c < 2048) {
            int cc = c - 1024; int hd = cc >> 7, dv = cc & 127;
            g_v[((size_t)(b * H_ + hd) * S_ + s) * DV_ + dv] = val;
        } else {
            int cc = c - 2048; int hd = cc >> 6, dk = cc & 63;
            float fv = fms[hd] * (val + fb[hd * DK_ + dk]);
            g_g[((size_t)(b * H_ + hd) * S_ + s) * DK_ + dk] = sigmoidf_(fv);
        }
    }
}

/* ------------------------------------------------------------------ */
/* recurrent scan: block = (kg, bh). 8 k-rows per block, 256 threads. */
/* ------------------------------------------------------------------ */
#define SCAN_SMEM ((128 * 132 + 2 * 1024 + 2 * 128) * 4)

__global__ void __launch_bounds__(256)
scan_kernel(const float* __restrict__ W)
{
    extern __shared__ float sm[];
    float* WT  = sm;                 /* 128*132 */
    float* Ssm = sm + 128 * 132;     /* 2*8*128 */
    float* yps = Ssm + 2048;         /* 2*128   */

    const int bh = blockIdx.y;
    const int kg = blockIdx.x;
    const int h  = bh & 7;
    const int tid = threadIdx.x;
    const int vcol  = tid & 127;
    const int khalf = tid >> 7;

    const float* Wh = W + (size_t)h * DV_ * DV_;
    for (int i = tid; i < DV_ * DV_; i += 256) {
        int u = i >> 7, w = i & 127;
        WT[w * 132 + u] = Wh[i];
    }
    for (int i = tid; i < 2048; i += 256) Ssm[i] = 0.f;
    __syncthreads();

    float s0 = 0.f, s1 = 0.f, s2 = 0.f, s3 = 0.f;

    const float* vb = g_v + (size_t)bh * S_ * DV_;
    const size_t qoffb = (size_t)bh * S_ * DK_ + kg * 8 + khalf * 4;
    const float* qb = g_q + qoffb;
    const float* kb = g_k + qoffb;
    const float* gb = g_g + qoffb;
    float* yo = g_yp + ((size_t)(kg * BH_ + bh) * S_) * DV_;

    const float4* wr = (const float4*)(WT + vcol * 132);
    int cur = 0;

    for (int t = 0; t < S_; t++) {
        const float4* Sb = (const float4*)(Ssm + cur * 1024 + khalf * 512);
        float p0 = 0.f, p1 = 0.f, p2 = 0.f, p3 = 0.f;
#pragma unroll
        for (int ug = 0; ug < 32; ug++) {
            float4 w4 = wr[ug];
            float4 a0 = Sb[ug];
            float4 a1 = Sb[32 + ug];
            float4 a2 = Sb[64 + ug];
            float4 a3 = Sb[96 + ug];
            p0 = fmaf(w4.x, a0.x, p0); p0 = fmaf(w4.y, a0.y, p0);
            p0 = fmaf(w4.z, a0.z, p0); p0 = fmaf(w4.w, a0.w, p0);
            p1 = fmaf(w4.x, a1.x, p1); p1 = fmaf(w4.y, a1.y, p1);
            p1 = fmaf(w4.z, a1.z, p1); p1 = fmaf(w4.w, a1.w, p1);
            p2 = fmaf(w4.x, a2.x, p2); p2 = fmaf(w4.y, a2.y, p2);
            p2 = fmaf(w4.z, a2.z, p2); p2 = fmaf(w4.w, a2.w, p2);
            p3 = fmaf(w4.x, a3.x, p3); p3 = fmaf(w4.y, a3.y, p3);
            p3 = fmaf(w4.z, a3.z, p3); p3 = fmaf(w4.w, a3.w, p3);
        }

        float vt = vb[t * DV_ + vcol];
        float4 q4 = *(const float4*)(qb + t * DK_);
        float4 k4 = *(const float4*)(kb + t * DK_);
        float4 g4 = *(const float4*)(gb + t * DK_);

        float c0 = tanhf(vt + p0); s0 = fmaf(g4.x, s0, k4.x * c0);
        float c1 = tanhf(vt + p1); s1 = fmaf(g4.y, s1, k4.y * c1);
        float c2 = tanhf(vt + p2); s2 = fmaf(g4.z, s2, k4.z * c2);
        float c3 = tanhf(vt + p3); s3 = fmaf(g4.w, s3, k4.w * c3);

        float ypv = q4.x * s0 + q4.y * s1 + q4.z * s2 + q4.w * s3;

        int nxt = cur ^ 1;
        float* Sw = Ssm + nxt * 1024 + khalf * 512 + vcol;
        Sw[0] = s0; Sw[128] = s1; Sw[256] = s2; Sw[384] = s3;
        if (khalf) yps[(t & 1) * 128 + vcol] = ypv;
        __syncthreads();
        if (!khalf) yo[t * DV_ + vcol] = ypv + yps[(t & 1) * 128 + vcol];
        cur = nxt;
    }
}

/* ------------------------------------------------------------------ */
/* reduce partials + v*D + gate*silu + RMSNorm*g_w                    */
/* ------------------------------------------------------------------ */
__global__ void __launch_bounds__(256)
mix_kernel(const float* __restrict__ Dm, const float* __restrict__ gw)
{
    const int bs = blockIdx.x;
    const int b = bs >> 10;
    const int s = bs & 1023;

    __shared__ float ybuf[GDIM];
    __shared__ float red[8];

    float local = 0.f;
    for (int c = threadIdx.x; c < GDIM; c += 256) {
        int hd = c >> 7, dv = c & 127;
        size_t bh = (size_t)b * H_ + hd;
        float acc = 0.f;
#pragma unroll
        for (int kg = 0; kg < KGROUPS; kg++)
            acc += g_yp[(((size_t)kg * BH_ + bh) * S_ + s) * DV_ + dv];
        float vv = g_v[(bh * S_ + s) * DV_ + dv];
        acc = fmaf(vv, Dm[hd * DV_ + dv], acc);
        float gt = g_h[(size_t)bs * HTOT + CONVDIM + c];
        acc *= gt * sigmoidf_(gt);
        ybuf[c] = acc;
        local = fmaf(acc, acc, local);
    }
#pragma unroll
    for (int o = 16; o; o >>= 1) local += __shfl_xor_sync(0xffffffffu, local, o);
    if ((threadIdx.x & 31) == 0) red[threadIdx.x >> 5] = local;
    __syncthreads();
    if (threadIdx.x == 0) {
        float tot = 0.f;
#pragma unroll
        for (int i = 0; i < 8; i++) tot += red[i];
        red[0] = rsqrtf(tot / (float)GDIM + 1e-6f);
    }
    __syncthreads();
    float rms = red[0];
    for (int c = threadIdx.x; c < GDIM; c += 256)
        g_y2[(size_t)bs * GDIM + c] = ybuf[c] * rms * gw[c];
}

/* ------------------------------------------------------------------ */
extern "C" void kernel_launch(void* const* d_in, const int* in_sizes, int n_in,
                              void* d_out, int out_size)
{
    const float* x    = (const float*)d_in[0];
    const float* w_in = (const float*)d_in[1];
    const float* b_in = (const float*)d_in[2];
    const float* cw   = (const float*)d_in[3];
    const float* cb   = (const float*)d_in[4];
    const float* Dm   = (const float*)d_in[5];
    const float* Wst  = (const float*)d_in[6];
    const float* fm   = (const float*)d_in[7];
    const float* fb   = (const float*)d_in[8];
    const float* gw   = (const float*)d_in[9];
    const float* wout = (const float*)d_in[10];
    float* out = (float*)d_out;

    void *ph = 0, *py2 = 0;
    cudaGetSymbolAddress(&ph, g_h);
    cudaGetSymbolAddress(&py2, g_y2);

    cudaFuncSetAttribute(scan_kernel, cudaFuncAttributeMaxDynamicSharedMemorySize, SCAN_SMEM);

    /* 1. in-projection: h = x @ w_in^T + b_in (tf32 tensor cores) */
    gemm_tf32<<<dim3(HTOT / 128, MTOT / 128), 256>>>(x, w_in, b_in, (float*)ph,
                                                     MTOT, HTOT, DIN, 1);
    /* 2. conv + silu + split + knorm + gate precompute */
    conv_split_kernel<<<MTOT, 256>>>(cw, cb, fm, fb);
    /* 3. recurrent scan (128 independent blocks) */
    scan_kernel<<<dim3(KGROUPS, BH_), 256, SCAN_SMEM>>>(Wst);
    /* 4. reduce + v*D + gate + RMSNorm */
    mix_kernel<<<MTOT, 256>>>(Dm, gw);
    /* 5. out-projection: out = y2 @ w_out^T (tf32 tensor cores) */
    gemm_tf32<<<dim3(DOUT / 128, MTOT / 128), 256>>>((const float*)py2, wout, 0, out,
                                                     MTOT, DOUT, GDIM, 0);
}

// round 4
// speedup vs baseline: 2.0362x; 1.8310x over previous
#include <cuda_runtime.h>
#include <math.h>

#define B_      2
#define S_      1024
#define DIN     2048
#define DOUT    2048
#define H_      8
#define DK_     64
#define DV_     128
#define CONVDIM 2560
#define GDIM    1024
#define HTOT    3584   /* CONVDIM + GDIM */
#define MTOT    2048   /* B_*S_ */
#define BH_     16     /* B_*H_ */
#define KGROUPS 8      /* DK_/8 */

/* ------------------------------------------------------------------ */
/* scratch (device globals; no runtime allocation allowed)            */
/* ------------------------------------------------------------------ */
__device__ float g_h [MTOT * HTOT];
__device__ float g_q [BH_ * S_ * DK_];
__device__ float g_k [BH_ * S_ * DK_];
__device__ float g_g [BH_ * S_ * DK_];
__device__ float g_v [BH_ * S_ * DV_];
__device__ float g_yp[KGROUPS * BH_ * S_ * DV_];
__device__ float g_y2[MTOT * GDIM];

__device__ __forceinline__ float sigmoidf_(float x) { return 1.f / (1.f + expf(-x)); }

__device__ __forceinline__ unsigned tf32_(float x) {
    unsigned r;
    asm("cvt.rna.tf32.f32 %0, %1;" : "=r"(r) : "f"(x));
    return r;
}

/* packed f32x2 helpers (Blackwell FFMA2 pipe) */
__device__ __forceinline__ unsigned long long fma2_(unsigned long long a,
                                                    unsigned long long b,
                                                    unsigned long long c) {
    unsigned long long d;
    asm("fma.rn.f32x2 %0, %1, %2, %3;" : "=l"(d) : "l"(a), "l"(b), "l"(c));
    return d;
}
__device__ __forceinline__ unsigned long long add2_(unsigned long long a,
                                                    unsigned long long b) {
    unsigned long long d;
    asm("add.rn.f32x2 %0, %1, %2;" : "=l"(d) : "l"(a), "l"(b));
    return d;
}
__device__ __forceinline__ unsigned long long pack2_(float lo, float hi) {
    unsigned long long d;
    asm("mov.b64 %0, {%1, %2};" : "=l"(d) : "f"(lo), "f"(hi));
    return d;
}
__device__ __forceinline__ float hsum2_(unsigned long long a) {
    float lo, hi;
    asm("mov.b64 {%0, %1}, %2;" : "=f"(lo), "=f"(hi) : "l"(a));
    return lo + hi;
}
__device__ __forceinline__ float tanh_fast_(float x) {
    float r;
    asm("tanh.approx.f32 %0, %1;" : "=f"(r) : "f"(x));
    return r;
}

/* ------------------------------------------------------------------ */
/* TF32 tensor-core GEMM (NT): C[M,N] = A[M,K] * B[N,K]^T (+ bias[N]) */
/* ------------------------------------------------------------------ */
#define GPITCH 36

__global__ void __launch_bounds__(256)
gemm_tf32(const float* __restrict__ A, const float* __restrict__ B,
          const float* __restrict__ bias, float* __restrict__ C,
          int M, int N, int K, int hasBias)
{
    __shared__ unsigned As[128 * GPITCH];
    __shared__ unsigned Bs[128 * GPITCH];

    const int tid  = threadIdx.x;
    const int lane = tid & 31;
    const int wid  = tid >> 5;
    const int warpM = wid & 1;
    const int warpN = wid >> 1;
    const int bm = blockIdx.y * 128;
    const int bn = blockIdx.x * 128;

    const int lrow  = tid >> 1;
    const int lkb   = (tid & 1) << 4;
    const float* Ag = A + (size_t)(bm + lrow) * K + lkb;
    const float* Bg = B + (size_t)(bn + lrow) * K + lkb;

    float acc[4][4][4];
#pragma unroll
    for (int i = 0; i < 4; i++)
#pragma unroll
        for (int j = 0; j < 4; j++)
#pragma unroll
            for (int r = 0; r < 4; r++) acc[i][j][r] = 0.f;

    const int nkt = K >> 5;

    float4 pa[4], pb[4];
#pragma unroll
    for (int i = 0; i < 4; i++) {
        pa[i] = *(const float4*)(Ag + i * 4);
        pb[i] = *(const float4*)(Bg + i * 4);
    }

    for (int kt = 0; kt < nkt; kt++) {
#pragma unroll
        for (int i = 0; i < 4; i++) {
            unsigned* pA = &As[lrow * GPITCH + lkb + i * 4];
            pA[0] = tf32_(pa[i].x); pA[1] = tf32_(pa[i].y);
            pA[2] = tf32_(pa[i].z); pA[3] = tf32_(pa[i].w);
            unsigned* pB = &Bs[lrow * GPITCH + lkb + i * 4];
            pB[0] = tf32_(pb[i].x); pB[1] = tf32_(pb[i].y);
            pB[2] = tf32_(pb[i].z); pB[3] = tf32_(pb[i].w);
        }
        __syncthreads();

        if (kt + 1 < nkt) {
            const float* Agn = Ag + (kt + 1) * 32;
            const float* Bgn = Bg + (kt + 1) * 32;
#pragma unroll
            for (int i = 0; i < 4; i++) {
                pa[i] = *(const float4*)(Agn + i * 4);
                pb[i] = *(const float4*)(Bgn + i * 4);
            }
        }

#pragma unroll
        for (int ks = 0; ks < 4; ks++) {
            const int kc = ks * 8 + (lane & 3);
            unsigned af[4][4], bf[4][2];
#pragma unroll
            for (int mt = 0; mt < 4; mt++) {
                int r = warpM * 64 + mt * 16 + (lane >> 2);
                af[mt][0] = As[r * GPITCH + kc];
                af[mt][1] = As[(r + 8) * GPITCH + kc];
                af[mt][2] = As[r * GPITCH + kc + 4];
                af[mt][3] = As[(r + 8) * GPITCH + kc + 4];
            }
#pragma unroll
            for (int nt = 0; nt < 4; nt++) {
                int r = warpN * 32 + nt * 8 + (lane >> 2);
                bf[nt][0] = Bs[r * GPITCH + kc];
                bf[nt][1] = Bs[r * GPITCH + kc + 4];
            }
#pragma unroll
            for (int mt = 0; mt < 4; mt++)
#pragma unroll
                for (int nt = 0; nt < 4; nt++) {
                    asm volatile(
                        "mma.sync.aligned.m16n8k8.row.col.f32.tf32.tf32.f32 "
                        "{%0,%1,%2,%3}, {%4,%5,%6,%7}, {%8,%9}, {%0,%1,%2,%3};"
                        : "+f"(acc[mt][nt][0]), "+f"(acc[mt][nt][1]),
                          "+f"(acc[mt][nt][2]), "+f"(acc[mt][nt][3])
                        : "r"(af[mt][0]), "r"(af[mt][1]),
                          "r"(af[mt][2]), "r"(af[mt][3]),
                          "r"(bf[nt][0]), "r"(bf[nt][1]));
                }
        }
        __syncthreads();
    }

#pragma unroll
    for (int mt = 0; mt < 4; mt++) {
        int row0 = bm + warpM * 64 + mt * 16 + (lane >> 2);
#pragma unroll
        for (int nt = 0; nt < 4; nt++) {
            int col = bn + warpN * 32 + nt * 8 + ((lane & 3) << 1);
            float b0 = hasBias ? bias[col] : 0.f;
            float b1 = hasBias ? bias[col + 1] : 0.f;
            float2 v0 = make_float2(acc[mt][nt][0] + b0, acc[mt][nt][1] + b1);
            float2 v1 = make_float2(acc[mt][nt][2] + b0, acc[mt][nt][3] + b1);
            *(float2*)(C + (size_t)row0 * N + col) = v0;
            *(float2*)(C + (size_t)(row0 + 8) * N + col) = v1;
        }
    }
}

/* ------------------------------------------------------------------ */
/* depthwise causal conv (K=4) + SiLU + split + k-norm + gate precomp */
/* ------------------------------------------------------------------ */
__global__ void __launch_bounds__(256)
conv_split_kernel(const float* __restrict__ cw, const float* __restrict__ cb,
                  const float* __restrict__ fm, const float* __restrict__ fb)
{
    const int bs = blockIdx.x;
    const int b = bs >> 10;
    const int s = bs & 1023;

    __shared__ float yc[CONVDIM];
    __shared__ float rn[H_];
    __shared__ float fms[H_];

    const float* hrow = g_h + (size_t)bs * HTOT;

    for (int c = threadIdx.x; c < CONVDIM; c += 256) {
        const float4 w4 = *(const float4*)(cw + c * 4);
        float acc = cb[c];
        if (s >= 3) acc += hrow[-3 * HTOT + c] * w4.x;
        if (s >= 2) acc += hrow[-2 * HTOT + c] * w4.y;
        if (s >= 1) acc += hrow[-1 * HTOT + c] * w4.z;
        acc += hrow[c] * w4.w;
        yc[c] = acc * sigmoidf_(acc);
    }
    __syncthreads();

    const int wid = threadIdx.x >> 5;
    const int lane = threadIdx.x & 31;
    {
        float a = yc[512 + wid * 64 + lane];
        float b2 = yc[512 + wid * 64 + 32 + lane];
        float ss = a * a + b2 * b2;
#pragma unroll
        for (int o = 16; o; o >>= 1) ss += __shfl_xor_sync(0xffffffffu, ss, o);
        if (lane == 0) {
            rn[wid] = rsqrtf(ss + 1e-12f);
            fms[wid] = 2.f * sigmoidf_(fm[wid]);
        }
    }
    __syncthreads();

    for (int c = threadIdx.x; c < CONVDIM; c += 256) {
        float val = yc[c];
        if (c < 512) {
            int hd = c >> 6, dk = c & 63;
            g_q[((size_t)(b * H_ + hd) * S_ + s) * DK_ + dk] = val;
        } else if (c < 1024) {
            int cc = c - 512; int hd = cc >> 6, dk = cc & 63;
            g_k[((size_t)(b * H_ + hd) * S_ + s) * DK_ + dk] = val * rn[hd];
        } else if (c < 2048) {
            int cc = c - 1024; int hd = cc >> 7, dv = cc & 127;
            g_v[((size_t)(b * H_ + hd) * S_ + s) * DV_ + dv] = val;
        } else {
            int cc = c - 2048; int hd = cc >> 6, dk = cc & 63;
            float fv = fms[hd] * (val + fb[hd * DK_ + dk]);
            g_g[((size_t)(b * H_ + hd) * S_ + s) * DK_ + dk] = sigmoidf_(fv);
        }
    }
}

/* ------------------------------------------------------------------ */
/* recurrent scan v2: FFMA2 + register-resident W column              */
/* block = (kg, bh), 256 threads. khalf = tid>>7 owns 4 k-rows,       */
/* vcol = tid&127 owns 1 output column. W[:,vcol] lives in 64 packed  */
/* f32x2 registers. S double-buffered in smem, read as ulonglong2     */
/* warp-broadcast. q/k/g/v prefetched one step ahead.                 */
/* ------------------------------------------------------------------ */
__global__ void __launch_bounds__(256)
scan_kernel(const float* __restrict__ W)
{
    __shared__ float Ssm[2][8][DV_];   /* [buf][k-row][col] */
    __shared__ float yps[2][DV_];

    const int bh = blockIdx.y;
    const int kg = blockIdx.x;
    const int h  = bh & 7;
    const int tid = threadIdx.x;
    const int vcol  = tid & 127;
    const int khalf = tid >> 7;

    /* W column -> registers, packed in u-pairs */
    const float* Wh = W + (size_t)h * DV_ * DV_ + vcol;
    unsigned long long wp[64];
#pragma unroll
    for (int i = 0; i < 64; i++)
        wp[i] = pack2_(Wh[(2 * i) * DV_], Wh[(2 * i + 1) * DV_]);

    for (int i = tid; i < 2 * 8 * DV_; i += 256)
        ((float*)Ssm)[i] = 0.f;
    __syncthreads();

    float s0 = 0.f, s1 = 0.f, s2 = 0.f, s3 = 0.f;

    const float* vb = g_v + (size_t)bh * S_ * DV_ + vcol;
    const size_t qoffb = (size_t)bh * S_ * DK_ + kg * 8 + khalf * 4;
    const float* qb = g_q + qoffb;
    const float* kb = g_k + qoffb;
    const float* gb = g_g + qoffb;
    float* yo = g_yp + ((size_t)(kg * BH_ + bh) * S_) * DV_ + vcol;

    /* current-step operands (prefetched) */
    float  vtc = vb[0];
    float4 qc = *(const float4*)(qb);
    float4 kc = *(const float4*)(kb);
    float4 gc = *(const float4*)(gb);

    int cur = 0;

    for (int t = 0; t < S_; t++) {
        /* prefetch next step */
        const int tn = (t + 1 < S_) ? (t + 1) : t;
        float  vtn = vb[tn * DV_];
        float4 qn = *(const float4*)(qb + tn * DK_);
        float4 kn = *(const float4*)(kb + tn * DK_);
        float4 gn = *(const float4*)(gb + tn * DK_);

        /* matvec: p[r] = sum_u S[k_r,u] * W[u,vcol], packed pairs */
        const ulonglong2* Sr0 = (const ulonglong2*)&Ssm[cur][khalf * 4 + 0][0];
        const ulonglong2* Sr1 = (const ulonglong2*)&Ssm[cur][khalf * 4 + 1][0];
        const ulonglong2* Sr2 = (const ulonglong2*)&Ssm[cur][khalf * 4 + 2][0];
        const ulonglong2* Sr3 = (const ulonglong2*)&Ssm[cur][khalf * 4 + 3][0];

        unsigned long long a0a = 0ull, a0b = 0ull, a1a = 0ull, a1b = 0ull;
        unsigned long long a2a = 0ull, a2b = 0ull, a3a = 0ull, a3b = 0ull;
#pragma unroll
        for (int i = 0; i < 32; i++) {
            ulonglong2 x0 = Sr0[i];
            ulonglong2 x1 = Sr1[i];
            ulonglong2 x2 = Sr2[i];
            ulonglong2 x3 = Sr3[i];
            a0a = fma2_(x0.x, wp[2 * i], a0a); a0b = fma2_(x0.y, wp[2 * i + 1], a0b);
            a1a = fma2_(x1.x, wp[2 * i], a1a); a1b = fma2_(x1.y, wp[2 * i + 1], a1b);
            a2a = fma2_(x2.x, wp[2 * i], a2a); a2b = fma2_(x2.y, wp[2 * i + 1], a2b);
            a3a = fma2_(x3.x, wp[2 * i], a3a); a3b = fma2_(x3.y, wp[2 * i + 1], a3b);
        }
        float p0 = hsum2_(add2_(a0a, a0b));
        float p1 = hsum2_(add2_(a1a, a1b));
        float p2 = hsum2_(add2_(a2a, a2b));
        float p3 = hsum2_(add2_(a3a, a3b));

        float c0 = tanh_fast_(vtc + p0); s0 = fmaf(gc.x, s0, kc.x * c0);
        float c1 = tanh_fast_(vtc + p1); s1 = fmaf(gc.y, s1, kc.y * c1);
        float c2 = tanh_fast_(vtc + p2); s2 = fmaf(gc.z, s2, kc.z * c2);
        float c3 = tanh_fast_(vtc + p3); s3 = fmaf(gc.w, s3, kc.w * c3);

        float ypv = qc.x * s0 + qc.y * s1 + qc.z * s2 + qc.w * s3;

        int nxt = cur ^ 1;
        Ssm[nxt][khalf * 4 + 0][vcol] = s0;
        Ssm[nxt][khalf * 4 + 1][vcol] = s1;
        Ssm[nxt][khalf * 4 + 2][vcol] = s2;
        Ssm[nxt][khalf * 4 + 3][vcol] = s3;
        if (khalf) yps[t & 1][vcol] = ypv;
        __syncthreads();
        if (!khalf) yo[t * DV_] = ypv + yps[t & 1][vcol];
        cur = nxt;

        vtc = vtn; qc = qn; kc = kn; gc = gn;
    }
}

/* ------------------------------------------------------------------ */
/* reduce partials + v*D + gate*silu + RMSNorm*g_w                    */
/* ------------------------------------------------------------------ */
__global__ void __launch_bounds__(256)
mix_kernel(const float* __restrict__ Dm, const float* __restrict__ gw)
{
    const int bs = blockIdx.x;
    const int b = bs >> 10;
    const int s = bs & 1023;

    __shared__ float ybuf[GDIM];
    __shared__ float red[8];

    float local = 0.f;
    for (int c = threadIdx.x; c < GDIM; c += 256) {
        int hd = c >> 7, dv = c & 127;
        size_t bh = (size_t)b * H_ + hd;
        float acc = 0.f;
#pragma unroll
        for (int kg = 0; kg < KGROUPS; kg++)
            acc += g_yp[(((size_t)kg * BH_ + bh) * S_ + s) * DV_ + dv];
        float vv = g_v[(bh * S_ + s) * DV_ + dv];
        acc = fmaf(vv, Dm[hd * DV_ + dv], acc);
        float gt = g_h[(size_t)bs * HTOT + CONVDIM + c];
        acc *= gt * sigmoidf_(gt);
        ybuf[c] = acc;
        local = fmaf(acc, acc, local);
    }
#pragma unroll
    for (int o = 16; o; o >>= 1) local += __shfl_xor_sync(0xffffffffu, local, o);
    if ((threadIdx.x & 31) == 0) red[threadIdx.x >> 5] = local;
    __syncthreads();
    if (threadIdx.x == 0) {
        float tot = 0.f;
#pragma unroll
        for (int i = 0; i < 8; i++) tot += red[i];
        red[0] = rsqrtf(tot / (float)GDIM + 1e-6f);
    }
    __syncthreads();
    float rms = red[0];
    for (int c = threadIdx.x; c < GDIM; c += 256)
        g_y2[(size_t)bs * GDIM + c] = ybuf[c] * rms * gw[c];
}

/* ------------------------------------------------------------------ */
extern "C" void kernel_launch(void* const* d_in, const int* in_sizes, int n_in,
                              void* d_out, int out_size)
{
    const float* x    = (const float*)d_in[0];
    const float* w_in = (const float*)d_in[1];
    const float* b_in = (const float*)d_in[2];
    const float* cw   = (const float*)d_in[3];
    const float* cb   = (const float*)d_in[4];
    const float* Dm   = (const float*)d_in[5];
    const float* Wst  = (const float*)d_in[6];
    const float* fm   = (const float*)d_in[7];
    const float* fb   = (const float*)d_in[8];
    const float* gw   = (const float*)d_in[9];
    const float* wout = (const float*)d_in[10];
    float* out = (float*)d_out;

    void *ph = 0, *py2 = 0;
    cudaGetSymbolAddress(&ph, g_h);
    cudaGetSymbolAddress(&py2, g_y2);

    /* 1. in-projection (tf32 tensor cores) */
    gemm_tf32<<<dim3(HTOT / 128, MTOT / 128), 256>>>(x, w_in, b_in, (float*)ph,
                                                     MTOT, HTOT, DIN, 1);
    /* 2. conv + silu + split + knorm + gate precompute */
    conv_split_kernel<<<MTOT, 256>>>(cw, cb, fm, fb);
    /* 3. recurrent scan (FFMA2 + register W) */
    scan_kernel<<<dim3(KGROUPS, BH_), 256>>>(Wst);
    /* 4. reduce + v*D + gate + RMSNorm */
    mix_kernel<<<MTOT, 256>>>(Dm, gw);
    /* 5. out-projection (tf32 tensor cores) */
    gemm_tf32<<<dim3(DOUT / 128, MTOT / 128), 256>>>((const float*)py2, wout, 0, out,
                                                     MTOT, DOUT, GDIM, 0);
}